// round 12
// baseline (speedup 1.0000x reference)
#include <cuda_runtime.h>
#include <cstdint>

#define KSZ 5
#define NBUCKETS 25
#define BATCH 8
#define CHANNELS 96
#define HEIGHT 192
#define WIDTH 192

#define BTX 16
#define BTY 16
#define NTHREADS (BTX*BTY)   // 256
#define PX 4
#define TILE_OW (BTX*PX)     // 64
#define TILE_OH BTY          // 16
#define HW (HEIGHT*WIDTH)

__global__ __launch_bounds__(NTHREADS, 2) void csconv2d_kernel(
    const float* __restrict__ input,        // [B,C,H,W]
    const float* __restrict__ kernel_bank,  // [25,5,5]
    const int* __restrict__ buckets,        // [B,H,W] int32
    float* __restrict__ output)             // [B,C,H,W]
{
    __shared__ __align__(16) float s_bank[640];

    const int tx = threadIdx.x;
    const int ty = threadIdx.y;
    const int tid = ty * BTX + tx;

    const int w0 = blockIdx.x * TILE_OW;
    const int h0 = blockIdx.y * TILE_OH;
    const int b  = blockIdx.z;

    const int h = h0 + ty;
    const int wbase = w0 + PX * tx;   // multiple of 4

    for (int i = tid; i < NBUCKETS * KSZ * KSZ; i += NTHREADS)
        s_bank[i] = kernel_bank[i];
    __syncthreads();   // the only block barrier in the kernel

    const int4 bk4 = *reinterpret_cast<const int4*>(
        &buckets[((long long)b * HEIGHT + h) * WIDTH + wbase]);
    int bkt[PX] = {bk4.x, bk4.y, bk4.z, bk4.w};
    #pragma unroll
    for (int p = 0; p < PX; p++)
        bkt[p] = min(max(bkt[p], 0), NBUCKETS - 1);

    float wk[PX * 25];
    #pragma unroll
    for (int p = 0; p < PX; p++)
        #pragma unroll
        for (int t = 0; t < 25; t++)
            wk[p * 25 + t] = s_bank[bkt[p] * 25 + t];

    const float* inb  = input  + (size_t)b * CHANNELS * HW;
    float*       outb = output + (size_t)b * CHANNELS * HW;

    // Iteration-invariant window geometry.
    // Rows: gh = h-2+i (i=0..4); Cols: four 2-float pairs starting at wbase-2+2k.
    // Pairs are even-aligned and never straddle the W=192 row boundary.
    int  rowoff[KSZ];
    bool rowok[KSZ];
    #pragma unroll
    for (int i = 0; i < KSZ; i++) {
        const int gh = h - 2 + i;
        rowok[i]  = ((unsigned)gh < HEIGHT);
        rowoff[i] = (rowok[i] ? gh : 0) * WIDTH;
    }
    int  coloff[4];
    bool colok[4];
    #pragma unroll
    for (int k = 0; k < 4; k++) {
        const int gw = wbase - 2 + 2 * k;
        colok[k]  = ((unsigned)gw < WIDTH);     // pair fully in or fully out
        coloff[k] = colok[k] ? gw : 0;
    }

    #pragma unroll 1
    for (int c = 0; c < CHANNELS; c++) {
        const float* chan = inb + (size_t)c * HW;

        float acc[PX] = {0.f, 0.f, 0.f, 0.f};

        #pragma unroll
        for (int i = 0; i < KSZ; i++) {
            const float* rp = chan + rowoff[i];
            float2 q[4];
            #pragma unroll
            for (int k = 0; k < 4; k++) {
                const bool ok = rowok[i] && colok[k];
                const float2* src = reinterpret_cast<const float2*>(rp + coloff[k]);
                q[k] = ok ? *src : make_float2(0.f, 0.f);
            }
            const float v[8] = {q[0].x, q[0].y, q[1].x, q[1].y,
                                q[2].x, q[2].y, q[3].x, q[3].y};
            #pragma unroll
            for (int p = 0; p < PX; p++)
                #pragma unroll
                for (int j = 0; j < KSZ; j++)
                    acc[p] = fmaf(v[p + j], wk[p * 25 + i * KSZ + j], acc[p]);
        }

        float4 o = {acc[0], acc[1], acc[2], acc[3]};
        *reinterpret_cast<float4*>(
            &outb[((size_t)c * HEIGHT + h) * WIDTH + wbase]) = o;
    }
}

extern "C" void kernel_launch(void* const* d_in, const int* in_sizes, int n_in,
                              void* d_out, int out_size)
{
    const float* input       = (const float*)d_in[0];
    const float* kernel_bank = (const float*)d_in[1];
    const int*   buckets     = (const int*)d_in[2];
    float*       output      = (float*)d_out;

    dim3 block(BTX, BTY, 1);
    dim3 grid(WIDTH / TILE_OW, HEIGHT / TILE_OH, BATCH);   // (3, 12, 8)
    csconv2d_kernel<<<grid, block>>>(input, kernel_bank, buckets, output);
}

// round 13
// speedup vs baseline: 2.4629x; 2.4629x over previous
#include <cuda_runtime.h>
#include <cstdint>

#define KSZ 5
#define NBUCKETS 25
#define BATCH 8
#define CHANNELS 96
#define HEIGHT 192
#define WIDTH 192

#define BTX 16
#define BTY 16
#define NTHREADS (BTX*BTY)   // 256
#define PX 4
#define GROUP 4              // channels per barrier group
#define SUB 2                // channels per accumulator sub-block
#define NBUF 2               // group buffers
#define TILE_OW (BTX*PX)     // 64
#define TILE_OH BTY          // 16
#define HALO 2
#define TROWS (TILE_OH + 2*HALO)   // 20
#define TCOLS (TILE_OW + 2*HALO)   // 68
#define TSTRIDE 72                 // floats per row (288B, 16B-aligned)
#define TILE_FLOATS (TROWS * TSTRIDE)   // 1440
#define NPAIRS (TROWS * (TCOLS/2))      // 680 8-byte pairs per channel tile
#define NGROUP (CHANNELS / GROUP)       // 24
#define NSLOT 3                         // ceil(680/256)

__device__ __forceinline__ void cp_async8(uint32_t smem_dst, const void* gptr, int src_bytes) {
    asm volatile("cp.async.ca.shared.global [%0], [%1], 8, %2;\n"
                 :: "r"(smem_dst), "l"(gptr), "r"(src_bytes));
}
__device__ __forceinline__ void cp_async_commit() {
    asm volatile("cp.async.commit_group;\n" ::: "memory");
}
template <int N>
__device__ __forceinline__ void cp_async_wait() {
    asm volatile("cp.async.wait_group %0;\n" :: "n"(N) : "memory");
}

__global__ __launch_bounds__(NTHREADS, 2) void csconv2d_kernel(
    const float* __restrict__ input,        // [B,C,H,W]
    const float* __restrict__ kernel_bank,  // [25,5,5]
    const int* __restrict__ buckets,        // [B,H,W] int32
    float* __restrict__ output)             // [B,C,H,W]
{
    __shared__ __align__(16) float s_tile[NBUF][GROUP][TILE_FLOATS];  // 46,080 B
    __shared__ __align__(16) float s_bank[640];                       // 2,560 B

    const int tx = threadIdx.x;
    const int ty = threadIdx.y;
    const int tid = ty * BTX + tx;

    const int w0 = blockIdx.x * TILE_OW;
    const int h0 = blockIdx.y * TILE_OH;
    const int b  = blockIdx.z;

    const int h = h0 + ty;
    const int wbase = w0 + PX * tx;

    for (int i = tid; i < NBUCKETS * KSZ * KSZ; i += NTHREADS)
        s_bank[i] = kernel_bank[i];
    __syncthreads();

    const int4 bk4 = *reinterpret_cast<const int4*>(
        &buckets[((long long)b * HEIGHT + h) * WIDTH + wbase]);
    int bkt[PX] = {bk4.x, bk4.y, bk4.z, bk4.w};
    #pragma unroll
    for (int p = 0; p < PX; p++)
        bkt[p] = min(max(bkt[p], 0), NBUCKETS - 1);

    float wk[PX * 25];
    #pragma unroll
    for (int p = 0; p < PX; p++)
        #pragma unroll
        for (int t = 0; t < 25; t++)
            wk[p * 25 + t] = s_bank[bkt[p] * 25 + t];

    const float* inb  = input  + (size_t)b * CHANNELS * HEIGHT * WIDTH;
    float*       outb = output + (size_t)b * CHANNELS * HEIGHT * WIDTH;

    const uint32_t s_tile_base = (uint32_t)__cvta_generic_to_shared(&s_tile[0][0][0]);

    // Iteration-invariant fill slots (8-byte pairs; even-aligned, never straddle
    // the W=192 row boundary; zfill for OOB).
    int      g_rel[NSLOT];
    uint32_t s_rel[NSLOT];
    int      nbytes[NSLOT];
    #pragma unroll
    for (int s = 0; s < NSLOT; s++) {
        const int idx = tid + s * NTHREADS;
        if (idx < NPAIRS) {
            const int r   = idx / (TCOLS / 2);
            const int col = (idx % (TCOLS / 2)) * 2;
            const int gh = h0 + r - HALO;
            const int gw = w0 + col - HALO;
            const bool ok = ((unsigned)gh < HEIGHT) & ((unsigned)gw < WIDTH);
            g_rel[s]  = ok ? (gh * WIDTH + gw) : 0;
            s_rel[s]  = (uint32_t)((r * TSTRIDE + col) * 4);
            nbytes[s] = ok ? 8 : 0;
        } else {
            g_rel[s] = 0; s_rel[s] = 0; nbytes[s] = -1;
        }
    }

    // Issue async fills for the GROUP channels starting at c0 into buffer buf.
    auto issue_group = [&](int c0, int buf) {
        #pragma unroll
        for (int cc = 0; cc < GROUP; cc++) {
            const float* chan = inb + (size_t)(c0 + cc) * (HEIGHT * WIDTH);
            const uint32_t sbase = s_tile_base
                + (uint32_t)((buf * GROUP + cc) * TILE_FLOATS * 4);
            #pragma unroll
            for (int s = 0; s < NSLOT; s++)
                if (nbytes[s] >= 0)
                    cp_async8(sbase + s_rel[s], chan + g_rel[s], nbytes[s]);
        }
        cp_async_commit();
    };

    issue_group(0, 0);

    #pragma unroll 1
    for (int g = 0; g < NGROUP; g++) {
        const int buf = g & 1;
        const int c0 = g * GROUP;

        cp_async_wait<0>();   // group g's fills have landed
        __syncthreads();      // visible to all threads; other buffer fully read

        if (g + 1 < NGROUP)
            issue_group(c0 + GROUP, buf ^ 1);   // lands during ~3200-cycle compute

        // Two 2-channel sub-blocks keep live accumulators at the R8 level.
        #pragma unroll
        for (int sb = 0; sb < GROUP / SUB; sb++) {
            float acc[SUB][PX];
            #pragma unroll
            for (int cc = 0; cc < SUB; cc++)
                #pragma unroll
                for (int p = 0; p < PX; p++) acc[cc][p] = 0.f;

            #pragma unroll
            for (int i = 0; i < KSZ; i++) {
                #pragma unroll
                for (int cc = 0; cc < SUB; cc++) {
                    const float* row =
                        &s_tile[buf][sb * SUB + cc][(ty + i) * TSTRIDE + PX * tx];
                    const float4 a  = *reinterpret_cast<const float4*>(row);
                    const float4 bq = *reinterpret_cast<const float4*>(row + 4);
                    const float v[8] = {a.x, a.y, a.z, a.w, bq.x, bq.y, bq.z, bq.w};
                    #pragma unroll
                    for (int p = 0; p < PX; p++)
                        #pragma unroll
                        for (int j = 0; j < KSZ; j++)
                            acc[cc][p] = fmaf(v[p + j], wk[p * 25 + i * KSZ + j], acc[cc][p]);
                }
            }

            #pragma unroll
            for (int cc = 0; cc < SUB; cc++) {
                float4 o = {acc[cc][0], acc[cc][1], acc[cc][2], acc[cc][3]};
                *reinterpret_cast<float4*>(
                    &outb[((size_t)(c0 + sb * SUB + cc) * HEIGHT + h) * WIDTH + wbase]) = o;
            }
        }
    }
}

extern "C" void kernel_launch(void* const* d_in, const int* in_sizes, int n_in,
                              void* d_out, int out_size)
{
    const float* input       = (const float*)d_in[0];
    const float* kernel_bank = (const float*)d_in[1];
    const int*   buckets     = (const int*)d_in[2];
    float*       output      = (float*)d_out;

    dim3 block(BTX, BTY, 1);
    dim3 grid(WIDTH / TILE_OW, HEIGHT / TILE_OH, BATCH);   // (3, 12, 8)
    csconv2d_kernel<<<grid, block>>>(input, kernel_bank, buckets, output);
}

// round 16
// speedup vs baseline: 2.8552x; 1.1593x over previous
#include <cuda_runtime.h>
#include <cstdint>

#define KSZ 5
#define NBUCKETS 25
#define BATCH 8
#define CHANNELS 96
#define HEIGHT 192
#define WIDTH 192

#define BTX 16
#define BTY 16
#define NTHREADS (BTX*BTY)   // 256
#define PX 4
#define CH 2
#define NBUF 4
#define TILE_OW (BTX*PX)     // 64
#define TILE_OH BTY          // 16
#define HALO 2
#define TROWS (TILE_OH + 2*HALO)   // 20
#define TCOLS (TILE_OW + 2*HALO)   // 68
#define TSTRIDE 72                 // floats per row (288B, 16B-aligned)
#define TILE_FLOATS (TROWS * TSTRIDE)
#define NPAIRS (TROWS * (TCOLS/2))  // 680 8-byte pairs
#define NITER (CHANNELS / CH)       // 48
#define NMAIN (NITER - 4)           // 44 = 4*11  (main loop, unroll 4)
#define NSLOT 3                     // ceil(680/256)

__device__ __forceinline__ void cp_async8(uint32_t smem_dst, const void* gptr, int src_bytes) {
    asm volatile("cp.async.ca.shared.global [%0], [%1], 8, %2;\n"
                 :: "r"(smem_dst), "l"(gptr), "r"(src_bytes));
}
__device__ __forceinline__ void cp_async_commit() {
    asm volatile("cp.async.commit_group;\n" ::: "memory");
}
template <int N>
__device__ __forceinline__ void cp_async_wait() {
    asm volatile("cp.async.wait_group %0;\n" :: "n"(N) : "memory");
}

__global__ __launch_bounds__(NTHREADS, 2) void csconv2d_kernel(
    const float* __restrict__ input,        // [B,C,H,W]
    const float* __restrict__ kernel_bank,  // [25,5,5]
    const int* __restrict__ buckets,        // [B,H,W] int32
    float* __restrict__ output)             // [B,C,H,W]
{
    __shared__ __align__(16) float s_tile[NBUF][CH][TILE_FLOATS];  // 46,080 B
    __shared__ __align__(16) float s_bank[640];

    const int tx = threadIdx.x;
    const int ty = threadIdx.y;
    const int tid = ty * BTX + tx;

    const int w0 = blockIdx.x * TILE_OW;
    const int h0 = blockIdx.y * TILE_OH;
    const int b  = blockIdx.z;

    const int h = h0 + ty;
    const int wbase = w0 + PX * tx;

    for (int i = tid; i < NBUCKETS * KSZ * KSZ; i += NTHREADS)
        s_bank[i] = kernel_bank[i];
    __syncthreads();

    const int4 bk4 = *reinterpret_cast<const int4*>(
        &buckets[((long long)b * HEIGHT + h) * WIDTH + wbase]);
    int bkt[PX] = {bk4.x, bk4.y, bk4.z, bk4.w};
    #pragma unroll
    for (int p = 0; p < PX; p++)
        bkt[p] = min(max(bkt[p], 0), NBUCKETS - 1);

    float wk[PX * 25];
    #pragma unroll
    for (int p = 0; p < PX; p++)
        #pragma unroll
        for (int t = 0; t < 25; t++)
            wk[p * 25 + t] = s_bank[bkt[p] * 25 + t];

    const float* inb  = input  + (size_t)b * CHANNELS * HEIGHT * WIDTH;
    float*       outb = output + (size_t)b * CHANNELS * HEIGHT * WIDTH;

    const uint32_t s_tile_base = (uint32_t)__cvta_generic_to_shared(&s_tile[0][0][0]);

    // Iteration-invariant fill slots (8-byte pairs; even-aligned, never straddle
    // the W=192 row boundary; zfill for OOB rows/cols).
    int      g_rel[NSLOT];
    uint32_t s_rel[NSLOT];
    int      nbytes[NSLOT];
    #pragma unroll
    for (int s = 0; s < NSLOT; s++) {
        const int idx = tid + s * NTHREADS;
        if (idx < NPAIRS) {
            const int r   = idx / (TCOLS / 2);
            const int col = (idx % (TCOLS / 2)) * 2;
            const int gh = h0 + r - HALO;
            const int gw = w0 + col - HALO;
            const bool ok = ((unsigned)gh < HEIGHT) & ((unsigned)gw < WIDTH);
            g_rel[s]  = ok ? (gh * WIDTH + gw) : 0;
            s_rel[s]  = (uint32_t)((r * TSTRIDE + col) * 4);
            nbytes[s] = ok ? 8 : 0;
        } else {
            g_rel[s] = 0; s_rel[s] = 0; nbytes[s] = -1;
        }
    }

    auto issue_pair = [&](int c0, int buf) {
        #pragma unroll
        for (int cc = 0; cc < CH; cc++) {
            const float* chan = inb + (size_t)(c0 + cc) * (HEIGHT * WIDTH);
            const uint32_t sbase = s_tile_base
                + (uint32_t)((buf * CH + cc) * TILE_FLOATS * 4);
            #pragma unroll
            for (int s = 0; s < NSLOT; s++)
                if (nbytes[s] >= 0)
                    cp_async8(sbase + s_rel[s], chan + g_rel[s], nbytes[s]);
        }
        cp_async_commit();
    };

    // One iteration body; buf is compile-time-foldable under unroll.
    auto body = [&](int it, int buf) {
        const int c0 = it * CH;

        if (it + 3 < NITER)
            issue_pair(c0 + 3 * CH, (it + 3) & (NBUF - 1));

        float acc[CH][PX];
        #pragma unroll
        for (int cc = 0; cc < CH; cc++)
            #pragma unroll
            for (int p = 0; p < PX; p++) acc[cc][p] = 0.f;

        #pragma unroll
        for (int i = 0; i < KSZ; i++) {
            #pragma unroll
            for (int cc = 0; cc < CH; cc++) {
                const float* row = &s_tile[buf][cc][(ty + i) * TSTRIDE + PX * tx];
                const float4 a  = *reinterpret_cast<const float4*>(row);
                const float4 bq = *reinterpret_cast<const float4*>(row + 4);
                const float v[8] = {a.x, a.y, a.z, a.w, bq.x, bq.y, bq.z, bq.w};
                #pragma unroll
                for (int p = 0; p < PX; p++)
                    #pragma unroll
                    for (int j = 0; j < KSZ; j++)
                        acc[cc][p] = fmaf(v[p + j], wk[p * 25 + i * KSZ + j], acc[cc][p]);
            }
        }

        #pragma unroll
        for (int cc = 0; cc < CH; cc++) {
            float4 o = {acc[cc][0], acc[cc][1], acc[cc][2], acc[cc][3]};
            *reinterpret_cast<float4*>(
                &outb[((size_t)(c0 + cc) * HEIGHT + h) * WIDTH + wbase]) = o;
        }
    };

    // Prologue: 3 groups in flight.
    issue_pair(0, 0);
    issue_pair(CH, 1);
    issue_pair(2 * CH, 2);

    // Main loop: 44 iterations (= 4*11); wait<2> always valid here.
    #pragma unroll 4
    for (int it = 0; it < NMAIN; it++) {
        cp_async_wait<2>();
        __syncthreads();
        body(it, it & (NBUF - 1));
    }

    // Peeled tail: 4 iterations with decreasing outstanding groups.
    {
        cp_async_wait<2>(); __syncthreads(); body(NMAIN + 0, (NMAIN + 0) & (NBUF - 1));
        cp_async_wait<2>(); __syncthreads(); body(NMAIN + 1, (NMAIN + 1) & (NBUF - 1));
        cp_async_wait<1>(); __syncthreads(); body(NMAIN + 2, (NMAIN + 2) & (NBUF - 1));
        cp_async_wait<0>(); __syncthreads(); body(NMAIN + 3, (NMAIN + 3) & (NBUF - 1));
    }
}

extern "C" void kernel_launch(void* const* d_in, const int* in_sizes, int n_in,
                              void* d_out, int out_size)
{
    const float* input       = (const float*)d_in[0];
    const float* kernel_bank = (const float*)d_in[1];
    const int*   buckets     = (const int*)d_in[2];
    float*       output      = (float*)d_out;

    dim3 block(BTX, BTY, 1);
    dim3 grid(WIDTH / TILE_OW, HEIGHT / TILE_OH, BATCH);   // (3, 12, 8)
    csconv2d_kernel<<<grid, block>>>(input, kernel_bank, buckets, output);
}

// round 17
// speedup vs baseline: 3.1755x; 1.1122x over previous
#include <cuda_runtime.h>
#include <cstdint>

#define KSZ 5
#define NBUCKETS 25
#define BATCH 8
#define CHANNELS 96
#define HEIGHT 192
#define WIDTH 192
#define HW (HEIGHT*WIDTH)

#define BTX 16
#define BTY 16
#define NTHREADS (BTX*BTY)   // 256
#define PX 4
#define CH 2
#define NBUF 4
#define TILE_OW (BTX*PX)     // 64
#define TILE_OH BTY          // 16
#define HALO 2
#define TROWS (TILE_OH + 2*HALO)   // 20
#define TCOLS (TILE_OW + 2*HALO)   // 68
#define TSTRIDE 72                 // floats per row (288B, 16B-aligned)
#define TILE_FLOATS (TROWS * TSTRIDE)
#define NPAIRS (TROWS * (TCOLS/2))  // 680 8-byte pairs
#define NITER (CHANNELS / CH)       // 48
#define NMAIN (NITER - 4)           // 44 = 4*11  (main loop, unroll 4)
#define NSLOT 3                     // ceil(680/256)

__device__ __forceinline__ void cp_async8(uint32_t smem_dst, const void* gptr, int src_bytes) {
    asm volatile("cp.async.ca.shared.global [%0], [%1], 8, %2;\n"
                 :: "r"(smem_dst), "l"(gptr), "r"(src_bytes));
}
__device__ __forceinline__ void cp_async_commit() {
    asm volatile("cp.async.commit_group;\n" ::: "memory");
}
template <int N>
__device__ __forceinline__ void cp_async_wait() {
    asm volatile("cp.async.wait_group %0;\n" :: "n"(N) : "memory");
}

__global__ __launch_bounds__(NTHREADS, 2) void csconv2d_kernel(
    const float* __restrict__ input,        // [B,C,H,W]
    const float* __restrict__ kernel_bank,  // [25,5,5]
    const int* __restrict__ buckets,        // [B,H,W] int32
    float* __restrict__ output)             // [B,C,H,W]
{
    __shared__ __align__(16) float s_tile[NBUF][CH][TILE_FLOATS];  // 46,080 B
    __shared__ __align__(16) float s_bank[640];

    const int tx = threadIdx.x;
    const int ty = threadIdx.y;
    const int tid = ty * BTX + tx;

    const int w0 = blockIdx.x * TILE_OW;
    const int h0 = blockIdx.y * TILE_OH;
    const int b  = blockIdx.z;

    const int h = h0 + ty;
    const int wbase = w0 + PX * tx;

    for (int i = tid; i < NBUCKETS * KSZ * KSZ; i += NTHREADS)
        s_bank[i] = kernel_bank[i];
    __syncthreads();

    const int4 bk4 = *reinterpret_cast<const int4*>(
        &buckets[((long long)b * HEIGHT + h) * WIDTH + wbase]);
    int bkt[PX] = {bk4.x, bk4.y, bk4.z, bk4.w};
    #pragma unroll
    for (int p = 0; p < PX; p++)
        bkt[p] = min(max(bkt[p], 0), NBUCKETS - 1);

    float wk[PX * 25];
    #pragma unroll
    for (int p = 0; p < PX; p++)
        #pragma unroll
        for (int t = 0; t < 25; t++)
            wk[p * 25 + t] = s_bank[bkt[p] * 25 + t];

    const float* inb = input + (size_t)b * CHANNELS * HW;

    const uint32_t s_tile_base = (uint32_t)__cvta_generic_to_shared(&s_tile[0][0][0]);

    // Iteration-invariant fill slots (8-byte pairs; even-aligned, never straddle
    // the W=192 row boundary; zfill for OOB rows/cols).
    uint32_t s_rel[NSLOT];     // smem offset within a channel tile (bytes)
    int      nbytes[NSLOT];    // 8, 0 (zfill) or -1 (inactive)
    const float* gptr[NSLOT];  // RUNNING gmem pointer: advanced CH*HW per issued group
    #pragma unroll
    for (int s = 0; s < NSLOT; s++) {
        const int idx = tid + s * NTHREADS;
        if (idx < NPAIRS) {
            const int r   = idx / (TCOLS / 2);
            const int col = (idx % (TCOLS / 2)) * 2;
            const int gh = h0 + r - HALO;
            const int gw = w0 + col - HALO;
            const bool ok = ((unsigned)gh < HEIGHT) & ((unsigned)gw < WIDTH);
            gptr[s]   = inb + (ok ? (gh * WIDTH + gw) : 0);
            s_rel[s]  = (uint32_t)((r * TSTRIDE + col) * 4);
            nbytes[s] = ok ? 8 : 0;
        } else {
            gptr[s] = inb; s_rel[s] = 0; nbytes[s] = -1;
        }
    }

    // Issue one CH-channel group into buffer buf using the running pointers,
    // then advance them. Groups are always issued in order 0,1,2,...,47.
    auto issue_next = [&](int buf) {
        #pragma unroll
        for (int cc = 0; cc < CH; cc++) {
            const uint32_t sbase = s_tile_base
                + (uint32_t)((buf * CH + cc) * TILE_FLOATS * 4);
            #pragma unroll
            for (int s = 0; s < NSLOT; s++)
                if (nbytes[s] >= 0)
                    cp_async8(sbase + s_rel[s], gptr[s] + cc * HW, nbytes[s]);
        }
        cp_async_commit();
        #pragma unroll
        for (int s = 0; s < NSLOT; s++)
            gptr[s] += CH * HW;
    };

    // RUNNING output pointer for this thread (channel 0), advanced CH*HW per iter.
    float* outp = output + (size_t)b * CHANNELS * HW + (size_t)h * WIDTH + wbase;

    // One iteration body; buf compile-time-foldable under unroll.
    auto body = [&](int buf, bool do_issue) {
        if (do_issue)
            issue_next((buf + 3) & (NBUF - 1));

        float acc[CH][PX];
        #pragma unroll
        for (int cc = 0; cc < CH; cc++)
            #pragma unroll
            for (int p = 0; p < PX; p++) acc[cc][p] = 0.f;

        #pragma unroll
        for (int i = 0; i < KSZ; i++) {
            #pragma unroll
            for (int cc = 0; cc < CH; cc++) {
                const float* row = &s_tile[buf][cc][(ty + i) * TSTRIDE + PX * tx];
                const float4 a  = *reinterpret_cast<const float4*>(row);
                const float4 bq = *reinterpret_cast<const float4*>(row + 4);
                const float v[8] = {a.x, a.y, a.z, a.w, bq.x, bq.y, bq.z, bq.w};
                #pragma unroll
                for (int p = 0; p < PX; p++)
                    #pragma unroll
                    for (int j = 0; j < KSZ; j++)
                        acc[cc][p] = fmaf(v[p + j], wk[p * 25 + i * KSZ + j], acc[cc][p]);
            }
        }

        #pragma unroll
        for (int cc = 0; cc < CH; cc++) {
            float4 o = {acc[cc][0], acc[cc][1], acc[cc][2], acc[cc][3]};
            *reinterpret_cast<float4*>(outp + (size_t)cc * HW) = o;
        }
        outp += (size_t)CH * HW;
    };

    // Prologue: 3 groups in flight (groups 0,1,2 -> buffers 0,1,2).
    issue_next(0);
    issue_next(1);
    issue_next(2);

    // Main loop: 44 iterations (= 4*11); wait<2> always valid; always issues.
    #pragma unroll 4
    for (int it = 0; it < NMAIN; it++) {
        cp_async_wait<2>();
        __syncthreads();
        body(it & (NBUF - 1), true);
    }

    // Peeled tail: it = 44 (issues group 47), then 45,46,47 (no issue).
    cp_async_wait<2>(); __syncthreads(); body((NMAIN + 0) & (NBUF - 1), true);
    cp_async_wait<2>(); __syncthreads(); body((NMAIN + 1) & (NBUF - 1), false);
    cp_async_wait<1>(); __syncthreads(); body((NMAIN + 2) & (NBUF - 1), false);
    cp_async_wait<0>(); __syncthreads(); body((NMAIN + 3) & (NBUF - 1), false);
}

extern "C" void kernel_launch(void* const* d_in, const int* in_sizes, int n_in,
                              void* d_out, int out_size)
{
    const float* input       = (const float*)d_in[0];
    const float* kernel_bank = (const float*)d_in[1];
    const int*   buckets     = (const int*)d_in[2];
    float*       output      = (float*)d_out;

    dim3 block(BTX, BTY, 1);
    dim3 grid(WIDTH / TILE_OW, HEIGHT / TILE_OH, BATCH);   // (3, 12, 8)
    csconv2d_kernel<<<grid, block>>>(input, kernel_bank, buckets, output);
}